// round 3
// baseline (speedup 1.0000x reference)
#include <cuda_runtime.h>

#define FULLMASK 0xffffffffu

// scratch (allocation-free contract: __device__ globals)
__device__ float g_s[16384];        // softmax logits, one per (b, c)
__device__ float g_hfsel[512*128];  // hf row at agent_id per b
__device__ float g_red[2];          // softmax max, sumexp

__device__ __forceinline__ float wredsum(float v){
  #pragma unroll
  for(int o=16;o;o>>=1) v += __shfl_xor_sync(FULLMASK,v,o);
  return v;
}

typedef unsigned long long u64;

__device__ __forceinline__ u64 pack2(float lo, float hi){
  u64 r; asm("mov.b64 %0, {%1,%2};" : "=l"(r) : "f"(lo), "f"(hi)); return r;
}
__device__ __forceinline__ float2 unpack2(u64 v){
  float2 r; asm("mov.b64 {%0,%1}, %2;" : "=f"(r.x), "=f"(r.y) : "l"(v)); return r;
}
__device__ __forceinline__ void fma2(u64& d, u64 a, u64 b){
  asm("fma.rn.f32x2 %0, %1, %2, %0;" : "+l"(d) : "l"(a), "l"(b));
}

// ---- shared memory layout (floats) ----
#define OFF_W2   0        // 16384  linh_w[0] transposed+swizzled [h][k]
#define OFF_W3   16384    // 16384  linh_w[1] transposed+swizzled [h][k]
#define OFF_W1   32768    // 4096   lin1_w natural (later: fc2a_b, fc2b_w)
#define OFF_BASE 36864    // 4096   base[r][h]
#define OFF_HACC 40960    // 4096   h accumulator [c][h]
#define OFF_A    45056    // 8448   activation tile [edge][k], stride 132
#define OFF_EL   53504    // 1024   e values of active edges
#define OFF_LN1G 54528    // 128
#define OFF_LN1B 54656    // 128
#define OFF_LHB  54784    // 256    linh_b
#define OFF_LHG  55040    // 256    lnh_g
#define OFF_LHBB 55296    // 256    lnh_b
#define OFF_CL   55552    // 1024   (c<<5)|r of active edges (int)
#define OFF_MISC 56576    // 32     scan temporaries
#define SMEM_FLOATS 56608
#define SMEM_BYTES (SMEM_FLOATS*4)

#define A_STRIDE 132

__global__ __launch_bounds__(256,1)
void gnn_k1(const float* __restrict__ node_obs, const float* __restrict__ adj,
            const int* __restrict__ agent_id, const float* __restrict__ emb,
            const float* __restrict__ lin1_w, const float* __restrict__ lin1_b,
            const float* __restrict__ ln1_g, const float* __restrict__ ln1_b,
            const float* __restrict__ linh_w, const float* __restrict__ linh_b,
            const float* __restrict__ lnh_g, const float* __restrict__ lnh_b,
            const float* __restrict__ fc2a_w, const float* __restrict__ fc2a_b,
            const float* __restrict__ fc2b_w, const float* __restrict__ fc2b_b)
{
  extern __shared__ float sm[];
  float* sW2  = sm+OFF_W2;
  float* sW3  = sm+OFF_W3;
  float* sW1  = sm+OFF_W1;
  float* base = sm+OFF_BASE;
  float* hacc = sm+OFF_HACC;
  float* sA   = sm+OFF_A;
  float* elist= sm+OFF_EL;
  int*   clist=(int*)(sm+OFF_CL);
  float* sxj  = sA;                // alias: used only before tile loop
  int*   swsum=(int*)(sm+OFF_MISC);
  int*   swoff=swsum+8;
  int*   snact=swoff+8;

  const int b=blockIdx.x, t=threadIdx.x, lane=t&31, w=t>>5;

  // ---- weights: transpose [k][h] -> [h][k] with XOR swizzle, both layers ----
  // stored col: k' = (k&~3) ^ (4*((h>>2)&7))  |  + (k&3)
  {
    const float4* src=(const float4*)linh_w;
    for(int i=t;i<8192;i+=256){
      int l   = i>>12;
      int rem = i&4095;
      int k   = rem>>5;
      int h4  = (rem&31)*4;
      float4 v = src[i];
      float* dst = l? sW3 : sW2;
      int col = ((k&~3) ^ (4*((h4>>2)&7))) + (k&3);
      dst[(h4+0)*128 + col] = v.x;
      dst[(h4+1)*128 + col] = v.y;
      dst[(h4+2)*128 + col] = v.z;
      dst[(h4+3)*128 + col] = v.w;
    }
    const float4* s1=(const float4*)lin1_w; float4* d1=(float4*)sW1;
    for(int i=t;i<1024;i+=256) d1[i]=s1[i];
  }
  if(t<128){ sm[OFF_LN1G+t]=ln1_g[t]; sm[OFF_LN1B+t]=ln1_b[t]; }
  if(t<256){ sm[OFF_LHB+t]=linh_b[t]; sm[OFF_LHG+t]=lnh_g[t]; sm[OFF_LHBB+t]=lnh_b[t]; }
  for(int i=t;i<4096;i+=256) hacc[i]=0.f;

  // xj per r: 15 feats + 16-dim entity embedding
  if(t<32){
    const int r=t;
    const float* no = node_obs + (size_t)b*512 + r*16;
    #pragma unroll
    for(int k=0;k<15;k++) sxj[r*32+k]=no[k];
    int ent=(int)no[15];
    #pragma unroll
    for(int j=0;j<16;j++) sxj[r*32+15+j]=emb[ent*16+j];
    sxj[r*32+31]=0.f;
  }
  __syncthreads();

  // ---- base[r][h] = xj[r] @ W1[0:31] + b1 ----
  {
    const int h=t&127, r0=t>>7;
    for(int r=r0;r<32;r+=2){
      float acc=lin1_b[h];
      #pragma unroll
      for(int k=0;k<31;k++) acc += sxj[r*32+k]*sW1[k*128+h];
      base[r*128+h]=acc;
    }
  }

  // ---- edge compaction (c-major order), block scan ----
  float ev4[4]; int rc4[4]; int act4[4]; int cnt=0;
  #pragma unroll
  for(int q=0;q<4;q++){
    int idx=t*4+q; int c=idx>>5; int r=idx&31;
    float v=adj[(size_t)b*1024 + r*32 + c];
    int a=(v>0.f)&&(v<1.0f);
    act4[q]=a; ev4[q]=v; rc4[q]=(c<<5)|r; cnt+=a;
  }
  int x=cnt;
  #pragma unroll
  for(int o=1;o<32;o<<=1){int y=__shfl_up_sync(FULLMASK,x,o); if(lane>=o)x+=y;}
  if(lane==31) swsum[w]=x;
  __syncthreads();
  if(t==0){ int run=0;
    #pragma unroll
    for(int i=0;i<8;i++){ swoff[i]=run; run+=swsum[i]; }
    snact[0]=run;
  }
  __syncthreads();
  { int pos=swoff[w]+x-cnt;
    #pragma unroll
    for(int q=0;q<4;q++){ if(act4[q]){ clist[pos]=rc4[q]; elist[pos]=ev4[q]; pos++; } }
  }
  const int nact=snact[0];
  __syncthreads();   // base + edge list ready; sxj (alias of sA) now free

  const float4 w1l = *(const float4*)&sW1[31*128+lane*4];
  const float4 g1  = *(const float4*)&sm[OFF_LN1G+lane*4];
  const float4 b1v = *(const float4*)&sm[OFF_LN1B+lane*4];
  const int swzl = 4*(lane&7);   // weight swizzle offset for this lane

  const int nt=(nact+63)/64;
  const int colb=w*8;            // this warp's 8 edge columns

  for(int T=0;T<nt;T++){
    const int tb=T*64;
    // ---- layer 1: pre = base[r] + e*W1[31], relu, LN -> sA[e][h] ----
    #pragma unroll
    for(int jj=0;jj<8;jj++){
      int iloc=colb+jj, gi=tb+iloc;
      int r=0; float e=0.f;
      if(gi<nact){ int rc=clist[gi]; r=rc&31; e=elist[gi]; }
      float4 bs=*(const float4*)&base[r*128+lane*4];
      float vx=fmaxf(fmaf(e,w1l.x,bs.x),0.f);
      float vy=fmaxf(fmaf(e,w1l.y,bs.y),0.f);
      float vz=fmaxf(fmaf(e,w1l.z,bs.z),0.f);
      float vw=fmaxf(fmaf(e,w1l.w,bs.w),0.f);
      float s1=wredsum(vx+vy+vz+vw);
      float s2=wredsum(vx*vx+vy*vy+vz*vz+vw*vw);
      float mu=s1*(1.f/128.f);
      float inv=rsqrtf(s2*(1.f/128.f)-mu*mu+1e-5f);
      float4 o;
      o.x=(vx-mu)*inv*g1.x+b1v.x;
      o.y=(vy-mu)*inv*g1.y+b1v.y;
      o.z=(vz-mu)*inv*g1.z+b1v.z;
      o.w=(vw-mu)*inv*g1.w+b1v.w;
      *(float4*)&sA[iloc*A_STRIDE + lane*4] = o;
    }
    __syncwarp();
    // ---- two hidden layers, f32x2 packed over K parity ----
    #pragma unroll
    for(int l=0;l<2;l++){
      const float* Wt = l? sW3 : sW2;
      float4 bl=*(const float4*)&sm[OFF_LHB+l*128+lane*4];
      u64 acc2[8][4];
      #pragma unroll
      for(int e=0;e<8;e++){
        acc2[e][0]=pack2(bl.x,0.f); acc2[e][1]=pack2(bl.y,0.f);
        acc2[e][2]=pack2(bl.z,0.f); acc2[e][3]=pack2(bl.w,0.f);
      }
      const u64* Wrow0=(const u64*)&Wt[(lane*4+0)*128];
      const u64* Wrow1=(const u64*)&Wt[(lane*4+1)*128];
      const u64* Wrow2=(const u64*)&Wt[(lane*4+2)*128];
      const u64* Wrow3=(const u64*)&Wt[(lane*4+3)*128];
      #pragma unroll 2
      for(int kq=0;kq<32;kq++){
        const int k4=kq*4;
        const int kc=(k4^swzl)>>1;            // u64 index of swizzled quad
        ulonglong2 w0=*(const ulonglong2*)&Wrow0[kc];
        ulonglong2 w1q=*(const ulonglong2*)&Wrow1[kc];
        ulonglong2 w2=*(const ulonglong2*)&Wrow2[kc];
        ulonglong2 w3=*(const ulonglong2*)&Wrow3[kc];
        #pragma unroll
        for(int e=0;e<8;e++){
          ulonglong2 av=*(const ulonglong2*)&sA[(colb+e)*A_STRIDE + k4];
          fma2(acc2[e][0],av.x,w0.x);  fma2(acc2[e][0],av.y,w0.y);
          fma2(acc2[e][1],av.x,w1q.x); fma2(acc2[e][1],av.y,w1q.y);
          fma2(acc2[e][2],av.x,w2.x);  fma2(acc2[e][2],av.y,w2.y);
          fma2(acc2[e][3],av.x,w3.x);  fma2(acc2[e][3],av.y,w3.y);
        }
      }
      float4 gl =*(const float4*)&sm[OFF_LHG +l*128+lane*4];
      float4 bbl=*(const float4*)&sm[OFF_LHBB+l*128+lane*4];
      #pragma unroll
      for(int e=0;e<8;e++){
        float2 f0=unpack2(acc2[e][0]); float2 f1=unpack2(acc2[e][1]);
        float2 f2=unpack2(acc2[e][2]); float2 f3=unpack2(acc2[e][3]);
        float vx=fmaxf(f0.x+f0.y,0.f), vy=fmaxf(f1.x+f1.y,0.f);
        float vz=fmaxf(f2.x+f2.y,0.f), vw=fmaxf(f3.x+f3.y,0.f);
        float s1=wredsum(vx+vy+vz+vw);
        float s2=wredsum(vx*vx+vy*vy+vz*vz+vw*vw);
        float mu=s1*(1.f/128.f);
        float inv=rsqrtf(s2*(1.f/128.f)-mu*mu+1e-5f);
        float4 o;
        o.x=(vx-mu)*inv*gl.x+bbl.x;
        o.y=(vy-mu)*inv*gl.y+bbl.y;
        o.z=(vz-mu)*inv*gl.z+bbl.z;
        o.w=(vw-mu)*inv*gl.w+bbl.w;
        *(float4*)&sA[(colb+e)*A_STRIDE + lane*4] = o;
      }
      __syncwarp();
    }
    // ---- deterministic aggregation: h[c][h] += m[edge][h] ----
    __syncthreads();
    if(t<128){
      for(int i=0;i<64;i++){
        int gi=tb+i;
        if(gi>=nact) break;
        int c=clist[gi]>>5;
        hacc[c*128+t]+=sA[i*A_STRIDE+t];
      }
    }
    __syncthreads();
  }

  // ---- stage B: s[b,c] = relu(h @ fc2a + b2a) @ fc2b + b2b ----
  {
    const float4* s2=(const float4*)fc2a_w; float4* d2=(float4*)sW2;
    for(int i=t;i<4096;i+=256) d2[i]=s2[i];
    if(t<128){ sW1[t]=fc2a_b[t]; sW1[128+t]=fc2b_w[t]; }
  }
  __syncthreads();
  {
    float4 b2=*(const float4*)&sW1[lane*4];
    float4 f2=*(const float4*)&sW1[128+lane*4];
    float acc[4][4];
    #pragma unroll
    for(int cc=0;cc<4;cc++){acc[cc][0]=b2.x;acc[cc][1]=b2.y;acc[cc][2]=b2.z;acc[cc][3]=b2.w;}
    const int c0=w*4;
    #pragma unroll 4
    for(int k=0;k<128;k++){
      float4 wv=*(const float4*)&sW2[k*128+lane*4];
      #pragma unroll
      for(int cc=0;cc<4;cc++){
        float a=hacc[(c0+cc)*128+k];
        acc[cc][0]=fmaf(a,wv.x,acc[cc][0]);
        acc[cc][1]=fmaf(a,wv.y,acc[cc][1]);
        acc[cc][2]=fmaf(a,wv.z,acc[cc][2]);
        acc[cc][3]=fmaf(a,wv.w,acc[cc][3]);
      }
    }
    float b2b=fc2b_b[0];
    #pragma unroll
    for(int cc=0;cc<4;cc++){
      float p=fmaxf(acc[cc][0],0.f)*f2.x+fmaxf(acc[cc][1],0.f)*f2.y
             +fmaxf(acc[cc][2],0.f)*f2.z+fmaxf(acc[cc][3],0.f)*f2.w;
      p=wredsum(p);
      if(lane==0) g_s[b*32+c0+cc]=p+b2b;
    }
  }
  // stash the hf row this batch actually uses
  if(t<128){
    int ag=agent_id[b];
    g_hfsel[b*128+t]=hacc[ag*128+t];
  }
}

// ---- global softmax reduction over 16384 logits ----
__global__ void gnn_k2(){
  __shared__ float sw[8];
  int t=threadIdx.x, lane=t&31, w=t>>5;
  float m=-3.4e38f;
  for(int i=t;i<16384;i+=256) m=fmaxf(m,g_s[i]);
  #pragma unroll
  for(int o=16;o;o>>=1) m=fmaxf(m,__shfl_xor_sync(FULLMASK,m,o));
  if(lane==0) sw[w]=m;
  __syncthreads();
  float M=sw[0];
  #pragma unroll
  for(int i=1;i<8;i++) M=fmaxf(M,sw[i]);
  float acc=0.f;
  for(int i=t;i<16384;i+=256) acc+=expf(g_s[i]-M);
  acc=wredsum(acc);
  __syncthreads();
  if(lane==0) sw[w]=acc;
  __syncthreads();
  if(t==0){
    float S=0.f;
    #pragma unroll
    for(int i=0;i<8;i++) S+=sw[i];
    g_red[0]=M; g_red[1]=S;
  }
}

// ---- per-b head on the single selected row ----
__global__ __launch_bounds__(128)
void gnn_k3(const float* __restrict__ fc3_w, const float* __restrict__ fc3_b,
            const float* __restrict__ ln3_g, const float* __restrict__ ln3_b,
            const float* __restrict__ fc4_w, const float* __restrict__ fc4_b,
            const float* __restrict__ ln4_g, const float* __restrict__ ln4_b,
            const int* __restrict__ agent_id, float* __restrict__ out)
{
  __shared__ float shf[128], sy[128], sred[8];
  int b=blockIdx.x, t=threadIdx.x, lane=t&31, w=t>>5;
  shf[t]=g_hfsel[b*128+t];
  __syncthreads();
  float acc=fc3_b[t];
  #pragma unroll 4
  for(int k=0;k<128;k++) acc=fmaf(shf[k],fc3_w[k*128+t],acc);
  float v=fmaxf(acc,0.f);
  float s1=wredsum(v), s2=wredsum(v*v);
  if(lane==0){sred[w]=s1; sred[4+w]=s2;}
  __syncthreads();
  s1=sred[0]+sred[1]+sred[2]+sred[3];
  s2=sred[4]+sred[5]+sred[6]+sred[7];
  float mu=s1*(1.f/128.f);
  float inv=rsqrtf(s2*(1.f/128.f)-mu*mu+1e-5f);
  float vn=(v-mu)*inv*ln3_g[t]+ln3_b[t];
  int ag=agent_id[b];
  float alpha=expf(g_s[b*32+ag]-g_red[0])/g_red[1];
  sy[t]=alpha*vn;
  __syncthreads();
  acc=fc4_b[t];
  #pragma unroll 4
  for(int k=0;k<128;k++) acc=fmaf(sy[k],fc4_w[k*128+t],acc);
  v=fmaxf(acc,0.f);
  s1=wredsum(v); s2=wredsum(v*v);
  __syncthreads();
  if(lane==0){sred[w]=s1; sred[4+w]=s2;}
  __syncthreads();
  s1=sred[0]+sred[1]+sred[2]+sred[3];
  s2=sred[4]+sred[5]+sred[6]+sred[7];
  mu=s1*(1.f/128.f);
  inv=rsqrtf(s2*(1.f/128.f)-mu*mu+1e-5f);
  out[b*128+t]=(v-mu)*inv*ln4_g[t]+ln4_b[t];
}

extern "C" void kernel_launch(void* const* d_in, const int* in_sizes, int n_in,
                              void* d_out, int out_size)
{
  const float* node_obs=(const float*)d_in[0];
  const float* adj     =(const float*)d_in[1];
  const int*   agent_id=(const int*)  d_in[2];
  const float* emb     =(const float*)d_in[3];
  const float* lin1_w  =(const float*)d_in[4];
  const float* lin1_b  =(const float*)d_in[5];
  const float* ln1_g   =(const float*)d_in[6];
  const float* ln1_b   =(const float*)d_in[7];
  const float* linh_w  =(const float*)d_in[8];
  const float* linh_b  =(const float*)d_in[9];
  const float* lnh_g   =(const float*)d_in[10];
  const float* lnh_b   =(const float*)d_in[11];
  const float* fc2a_w  =(const float*)d_in[12];
  const float* fc2a_b  =(const float*)d_in[13];
  const float* fc2b_w  =(const float*)d_in[14];
  const float* fc2b_b  =(const float*)d_in[15];
  const float* fc3_w   =(const float*)d_in[16];
  const float* fc3_b   =(const float*)d_in[17];
  const float* ln3_g   =(const float*)d_in[18];
  const float* ln3_b   =(const float*)d_in[19];
  const float* fc4_w   =(const float*)d_in[20];
  const float* fc4_b   =(const float*)d_in[21];
  const float* ln4_g   =(const float*)d_in[22];
  const float* ln4_b   =(const float*)d_in[23];

  cudaFuncSetAttribute(gnn_k1, cudaFuncAttributeMaxDynamicSharedMemorySize, SMEM_BYTES);

  gnn_k1<<<512,256,SMEM_BYTES>>>(node_obs,adj,agent_id,emb,
                                 lin1_w,lin1_b,ln1_g,ln1_b,
                                 linh_w,linh_b,lnh_g,lnh_b,
                                 fc2a_w,fc2a_b,fc2b_w,fc2b_b);
  gnn_k2<<<1,256>>>();
  gnn_k3<<<512,128>>>(fc3_w,fc3_b,ln3_g,ln3_b,fc4_w,fc4_b,ln4_g,ln4_b,
                      agent_id,(float*)d_out);
}

// round 4
// speedup vs baseline: 1.0147x; 1.0147x over previous
#include <cuda_runtime.h>

#define FULLMASK 0xffffffffu

// scratch (allocation-free contract: __device__ globals)
__device__ float g_s[16384];        // softmax logits, one per (b, c)
__device__ float g_hfsel[512*128];  // hf row at agent_id per b
__device__ float g_red[2];          // softmax max, sumexp

__device__ __forceinline__ float wredsum(float v){
  #pragma unroll
  for(int o=16;o;o>>=1) v += __shfl_xor_sync(FULLMASK,v,o);
  return v;
}

typedef unsigned long long u64;

__device__ __forceinline__ u64 pack2(float lo, float hi){
  u64 r; asm("mov.b64 %0, {%1,%2};" : "=l"(r) : "f"(lo), "f"(hi)); return r;
}
__device__ __forceinline__ float2 unpack2(u64 v){
  float2 r; asm("mov.b64 {%0,%1}, %2;" : "=f"(r.x), "=f"(r.y) : "l"(v)); return r;
}
__device__ __forceinline__ void fma2(u64& d, u64 a, u64 b){
  asm("fma.rn.f32x2 %0, %1, %2, %0;" : "+l"(d) : "l"(a), "l"(b));
}

// ---- shared memory layout (floats) ----
#define OFF_W2   0        // 16384  linh_w[0] transposed+swizzled [h][k]
#define OFF_W3   16384    // 16384  linh_w[1] transposed+swizzled [h][k]
#define OFF_W1   32768    // 4096   lin1_w natural (later: fc2a_b, fc2b_w)
#define OFF_BASE 36864    // 4096   base[r][h]
#define OFF_HACC 40960    // 4096   h accumulator [c][h]
#define OFF_A    45056    // 8448   activation tile [edge][k], stride 132
#define OFF_EL   53504    // 1024   e values of active edges
#define OFF_LN1G 54528    // 128
#define OFF_LN1B 54656    // 128
#define OFF_LHB  54784    // 256    linh_b
#define OFF_LHG  55040    // 256    lnh_g
#define OFF_LHBB 55296    // 256    lnh_b
#define OFF_CL   55552    // 1024   (c<<5)|r of active edges (int)
#define OFF_MISC 56576    // 96     scount[32], sstart[33]
#define SMEM_FLOATS 56672
#define SMEM_BYTES (SMEM_FLOATS*4)

#define A_STRIDE 132

__global__ __launch_bounds__(512,1)
void gnn_k1(const float* __restrict__ node_obs, const float* __restrict__ adj,
            const int* __restrict__ agent_id, const float* __restrict__ emb,
            const float* __restrict__ lin1_w, const float* __restrict__ lin1_b,
            const float* __restrict__ ln1_g, const float* __restrict__ ln1_b,
            const float* __restrict__ linh_w, const float* __restrict__ linh_b,
            const float* __restrict__ lnh_g, const float* __restrict__ lnh_b,
            const float* __restrict__ fc2a_w, const float* __restrict__ fc2a_b,
            const float* __restrict__ fc2b_w, const float* __restrict__ fc2b_b)
{
  extern __shared__ float sm[];
  float* sW2  = sm+OFF_W2;
  float* sW3  = sm+OFF_W3;
  float* sW1  = sm+OFF_W1;
  float* base = sm+OFF_BASE;
  float* hacc = sm+OFF_HACC;
  float* sA   = sm+OFF_A;
  float* elist= sm+OFF_EL;
  int*   clist=(int*)(sm+OFF_CL);
  float* sxj  = sA;                // alias: used only before tile loop
  int*   scount=(int*)(sm+OFF_MISC);
  int*   sstart=scount+32;         // 33 entries

  const int b=blockIdx.x, t=threadIdx.x, lane=t&31, w=t>>5;

  // ---- weights: transpose [k][h] -> [h][k] with per-row XOR swizzle ----
  // element (k,h) stored at dst[h*128 + ((k&~3)^(4*(h&7))) + (k&3)]
  {
    const float4* src=(const float4*)linh_w;
    for(int i=t;i<8192;i+=512){
      int l   = i>>12;
      int rem = i&4095;
      int k   = rem>>5;
      int h4  = (rem&31)*4;
      float4 v = src[i];
      float* dst = l? sW3 : sW2;
      int kb=k&~3, kr=k&3;
      dst[(h4+0)*128 + ((kb^(4*((h4+0)&7)))+kr)] = v.x;
      dst[(h4+1)*128 + ((kb^(4*((h4+1)&7)))+kr)] = v.y;
      dst[(h4+2)*128 + ((kb^(4*((h4+2)&7)))+kr)] = v.z;
      dst[(h4+3)*128 + ((kb^(4*((h4+3)&7)))+kr)] = v.w;
    }
    const float4* s1=(const float4*)lin1_w; float4* d1=(float4*)sW1;
    for(int i=t;i<1024;i+=512) d1[i]=s1[i];
  }
  if(t<128){ sm[OFF_LN1G+t]=ln1_g[t]; sm[OFF_LN1B+t]=ln1_b[t]; }
  if(t<256){ sm[OFF_LHB+t]=linh_b[t]; sm[OFF_LHG+t]=lnh_g[t]; sm[OFF_LHBB+t]=lnh_b[t]; }

  // xj per r: 15 feats + 16-dim entity embedding  (sxj aliases sA)
  if(t<32){
    const int r=t;
    const float* no = node_obs + (size_t)b*512 + r*16;
    #pragma unroll
    for(int k=0;k<15;k++) sxj[r*32+k]=no[k];
    int ent=(int)no[15];
    #pragma unroll
    for(int j=0;j<16;j++) sxj[r*32+15+j]=emb[ent*16+j];
    sxj[r*32+31]=0.f;
  }
  __syncthreads();

  // ---- base[r][h] = xj[r] @ W1[0:31] + b1 ----
  {
    const int h=t&127, r0=t>>7;
    for(int r=r0;r<32;r+=4){
      float acc=lin1_b[h];
      #pragma unroll
      for(int k=0;k<31;k++) acc += sxj[r*32+k]*sW1[k*128+h];
      base[r*128+h]=acc;
    }
  }

  // ---- edge compaction (c-major), per-c counts via ballot ----
  float ev2[2]; int rc2[2]; int act2[2]; int cnt=0;
  #pragma unroll
  for(int q=0;q<2;q++){
    int idx=t*2+q; int c=idx>>5; int r=idx&31;
    float v=adj[(size_t)b*1024 + r*32 + c];
    int a=(v>0.f)&&(v<1.0f);
    act2[q]=a; ev2[q]=v; rc2[q]=(c<<5)|r; cnt+=a;
  }
  unsigned b0=__ballot_sync(FULLMASK,act2[0]);
  unsigned b1=__ballot_sync(FULLMASK,act2[1]);
  if(lane==0){
    scount[2*w]  =__popc(b0&0xffffu)+__popc(b1&0xffffu);
    scount[2*w+1]=__popc(b0>>16)+__popc(b1>>16);
  }
  int x=cnt;
  #pragma unroll
  for(int o=1;o<32;o<<=1){int y=__shfl_up_sync(FULLMASK,x,o); if(lane>=o)x+=y;}
  __syncthreads();
  if(t==0){
    int run=0;
    #pragma unroll
    for(int c=0;c<32;c++){ sstart[c]=run; run+=scount[c]; }
    sstart[32]=run;
  }
  __syncthreads();
  { int pos=sstart[2*w]+x-cnt;
    #pragma unroll
    for(int q=0;q<2;q++){ if(act2[q]){ clist[pos]=rc2[q]; elist[pos]=ev2[q]; pos++; } }
  }
  const int nact=sstart[32];
  __syncthreads();   // base + edge list ready; sxj (alias sA) now free

  // per-lane constants
  const float4 w1l = *(const float4*)&sW1[31*128+lane*4];
  const float4 g1  = *(const float4*)&sm[OFF_LN1G+lane*4];
  const float4 b1v = *(const float4*)&sm[OFF_LN1B+lane*4];
  const int eg = w&7;              // edge-group (8 edges)
  const int rh = w>>3;             // row-half (64 rows)
  const int rA = rh*64 + lane;     // GEMM row A
  const int rB = rA + 32;          // GEMM row B
  const int swz = 4*(lane&7);      // weight swizzle for rows ≡ lane (mod 8)
  const int c0agg = 2*w;           // this warp's 2 aggregation columns

  float agg[2][4];
  #pragma unroll
  for(int cc=0;cc<2;cc++){agg[cc][0]=0;agg[cc][1]=0;agg[cc][2]=0;agg[cc][3]=0;}

  const int nt=(nact+63)/64;
  for(int T=0;T<nt;T++){
    const int tb=T*64;
    // ---- layer 1: warp -> 4 edges, in-warp LN, write sA[e][h] ----
    #pragma unroll
    for(int j=0;j<4;j++){
      int iloc=w*4+j, gi=tb+iloc;
      int r=0; float e=0.f;
      if(gi<nact){ int rc=clist[gi]; r=rc&31; e=elist[gi]; }
      float4 bs=*(const float4*)&base[r*128+lane*4];
      float vx=fmaxf(fmaf(e,w1l.x,bs.x),0.f);
      float vy=fmaxf(fmaf(e,w1l.y,bs.y),0.f);
      float vz=fmaxf(fmaf(e,w1l.z,bs.z),0.f);
      float vw=fmaxf(fmaf(e,w1l.w,bs.w),0.f);
      float s1=wredsum(vx+vy+vz+vw);
      float s2=wredsum(vx*vx+vy*vy+vz*vz+vw*vw);
      float mu=s1*(1.f/128.f);
      float inv=rsqrtf(s2*(1.f/128.f)-mu*mu+1e-5f);
      float4 o;
      o.x=(vx-mu)*inv*g1.x+b1v.x;
      o.y=(vy-mu)*inv*g1.y+b1v.y;
      o.z=(vz-mu)*inv*g1.z+b1v.z;
      o.w=(vw-mu)*inv*g1.w+b1v.w;
      *(float4*)&sA[iloc*A_STRIDE + lane*4] = o;
    }
    __syncthreads();
    // ---- two hidden layers ----
    #pragma unroll
    for(int l=0;l<2;l++){
      const float* Wt = l? sW3 : sW2;
      u64 acc2[8][2];
      #pragma unroll
      for(int e=0;e<8;e++){ acc2[e][0]=0ull; acc2[e][1]=0ull; }
      const float* WrA=&Wt[rA*128];
      const float* WrB=&Wt[rB*128];
      const float* Ae =&sA[(eg*8)*A_STRIDE];
      #pragma unroll 4
      for(int kq=0;kq<32;kq++){
        const int k4=kq*4;
        const int kc=k4^swz;
        ulonglong2 wa=*(const ulonglong2*)&WrA[kc];
        ulonglong2 wb=*(const ulonglong2*)&WrB[kc];
        #pragma unroll
        for(int e=0;e<8;e++){
          ulonglong2 av=*(const ulonglong2*)&Ae[e*A_STRIDE + k4];
          fma2(acc2[e][0],av.x,wa.x); fma2(acc2[e][0],av.y,wa.y);
          fma2(acc2[e][1],av.x,wb.x); fma2(acc2[e][1],av.y,wb.y);
        }
      }
      __syncthreads();   // all activation reads complete before overwrite
      float bA=sm[OFF_LHB+l*128+rA], bB=sm[OFF_LHB+l*128+rB];
      #pragma unroll
      for(int e=0;e<8;e++){
        float2 fa=unpack2(acc2[e][0]);
        float2 fb=unpack2(acc2[e][1]);
        sA[(eg*8+e)*A_STRIDE + rA] = fa.x+fa.y+bA;
        sA[(eg*8+e)*A_STRIDE + rB] = fb.x+fb.y+bB;
      }
      __syncthreads();
      // LN pass: warp -> 4 edges
      float4 gl =*(const float4*)&sm[OFF_LHG +l*128+lane*4];
      float4 bbl=*(const float4*)&sm[OFF_LHBB+l*128+lane*4];
      #pragma unroll
      for(int j=0;j<4;j++){
        int iloc=w*4+j;
        float4 vv=*(const float4*)&sA[iloc*A_STRIDE + lane*4];
        float vx=fmaxf(vv.x,0.f), vy=fmaxf(vv.y,0.f);
        float vz=fmaxf(vv.z,0.f), vw=fmaxf(vv.w,0.f);
        float s1=wredsum(vx+vy+vz+vw);
        float s2=wredsum(vx*vx+vy*vy+vz*vz+vw*vw);
        float mu=s1*(1.f/128.f);
        float inv=rsqrtf(s2*(1.f/128.f)-mu*mu+1e-5f);
        float4 o;
        o.x=(vx-mu)*inv*gl.x+bbl.x;
        o.y=(vy-mu)*inv*gl.y+bbl.y;
        o.z=(vz-mu)*inv*gl.z+bbl.z;
        o.w=(vw-mu)*inv*gl.w+bbl.w;
        *(float4*)&sA[iloc*A_STRIDE + lane*4] = o;
      }
      __syncthreads();
    }
    // ---- segmented aggregation: warp owns columns c0agg, c0agg+1 ----
    #pragma unroll
    for(int cc=0;cc<2;cc++){
      int c=c0agg+cc;
      int lo=sstart[c];   if(lo<tb) lo=tb;
      int hi=sstart[c+1]; if(hi>tb+64) hi=tb+64;
      for(int i=lo;i<hi;i++){
        float4 f=*(const float4*)&sA[(i-tb)*A_STRIDE + lane*4];
        agg[cc][0]+=f.x; agg[cc][1]+=f.y; agg[cc][2]+=f.z; agg[cc][3]+=f.w;
      }
    }
    __syncthreads();   // aggregation reads done before next tile's L1 writes
  }

  // commit aggregation to smem
  #pragma unroll
  for(int cc=0;cc<2;cc++){
    float4 o; o.x=agg[cc][0]; o.y=agg[cc][1]; o.z=agg[cc][2]; o.w=agg[cc][3];
    *(float4*)&hacc[(c0agg+cc)*128 + lane*4] = o;
  }

  // ---- stage B: s[b,c] = relu(h @ fc2a + b2a) @ fc2b + b2b ----
  {
    const float4* s2=(const float4*)fc2a_w; float4* d2=(float4*)sW2;
    for(int i=t;i<4096;i+=512) d2[i]=s2[i];
    if(t<128){ sW1[t]=fc2a_b[t]; sW1[128+t]=fc2b_w[t]; }
  }
  __syncthreads();
  {
    float4 b2=*(const float4*)&sW1[lane*4];
    float4 f2=*(const float4*)&sW1[128+lane*4];
    float acc[2][4];
    #pragma unroll
    for(int cc=0;cc<2;cc++){acc[cc][0]=b2.x;acc[cc][1]=b2.y;acc[cc][2]=b2.z;acc[cc][3]=b2.w;}
    #pragma unroll 4
    for(int k=0;k<128;k++){
      float4 wv=*(const float4*)&sW2[k*128+lane*4];
      #pragma unroll
      for(int cc=0;cc<2;cc++){
        float a=hacc[(c0agg+cc)*128+k];
        acc[cc][0]=fmaf(a,wv.x,acc[cc][0]);
        acc[cc][1]=fmaf(a,wv.y,acc[cc][1]);
        acc[cc][2]=fmaf(a,wv.z,acc[cc][2]);
        acc[cc][3]=fmaf(a,wv.w,acc[cc][3]);
      }
    }
    float b2b=fc2b_b[0];
    #pragma unroll
    for(int cc=0;cc<2;cc++){
      float p=fmaxf(acc[cc][0],0.f)*f2.x+fmaxf(acc[cc][1],0.f)*f2.y
             +fmaxf(acc[cc][2],0.f)*f2.z+fmaxf(acc[cc][3],0.f)*f2.w;
      p=wredsum(p);
      if(lane==0) g_s[b*32+c0agg+cc]=p+b2b;
    }
  }
  // stash the hf row this batch actually uses
  if(t<128){
    int ag=agent_id[b];
    g_hfsel[b*128+t]=hacc[ag*128+t];
  }
}

// ---- global softmax reduction over 16384 logits ----
__global__ void gnn_k2(){
  __shared__ float sw[8];
  int t=threadIdx.x, lane=t&31, w=t>>5;
  float m=-3.4e38f;
  for(int i=t;i<16384;i+=256) m=fmaxf(m,g_s[i]);
  #pragma unroll
  for(int o=16;o;o>>=1) m=fmaxf(m,__shfl_xor_sync(FULLMASK,m,o));
  if(lane==0) sw[w]=m;
  __syncthreads();
  float M=sw[0];
  #pragma unroll
  for(int i=1;i<8;i++) M=fmaxf(M,sw[i]);
  float acc=0.f;
  for(int i=t;i<16384;i+=256) acc+=expf(g_s[i]-M);
  acc=wredsum(acc);
  __syncthreads();
  if(lane==0) sw[w]=acc;
  __syncthreads();
  if(t==0){
    float S=0.f;
    #pragma unroll
    for(int i=0;i<8;i++) S+=sw[i];
    g_red[0]=M; g_red[1]=S;
  }
}

// ---- per-b head on the single selected row ----
__global__ __launch_bounds__(128)
void gnn_k3(const float* __restrict__ fc3_w, const float* __restrict__ fc3_b,
            const float* __restrict__ ln3_g, const float* __restrict__ ln3_b,
            const float* __restrict__ fc4_w, const float* __restrict__ fc4_b,
            const float* __restrict__ ln4_g, const float* __restrict__ ln4_b,
            const int* __restrict__ agent_id, float* __restrict__ out)
{
  __shared__ float shf[128], sy[128], sred[8];
  int b=blockIdx.x, t=threadIdx.x, lane=t&31, w=t>>5;
  shf[t]=g_hfsel[b*128+t];
  __syncthreads();
  float acc=fc3_b[t];
  #pragma unroll 4
  for(int k=0;k<128;k++) acc=fmaf(shf[k],fc3_w[k*128+t],acc);
  float v=fmaxf(acc,0.f);
  float s1=wredsum(v), s2=wredsum(v*v);
  if(lane==0){sred[w]=s1; sred[4+w]=s2;}
  __syncthreads();
  s1=sred[0]+sred[1]+sred[2]+sred[3];
  s2=sred[4]+sred[5]+sred[6]+sred[7];
  float mu=s1*(1.f/128.f);
  float inv=rsqrtf(s2*(1.f/128.f)-mu*mu+1e-5f);
  float vn=(v-mu)*inv*ln3_g[t]+ln3_b[t];
  int ag=agent_id[b];
  float alpha=expf(g_s[b*32+ag]-g_red[0])/g_red[1];
  sy[t]=alpha*vn;
  __syncthreads();
  acc=fc4_b[t];
  #pragma unroll 4
  for(int k=0;k<128;k++) acc=fmaf(sy[k],fc4_w[k*128+t],acc);
  v=fmaxf(acc,0.f);
  s1=wredsum(v); s2=wredsum(v*v);
  __syncthreads();
  if(lane==0){sred[w]=s1; sred[4+w]=s2;}
  __syncthreads();
  s1=sred[0]+sred[1]+sred[2]+sred[3];
  s2=sred[4]+sred[5]+sred[6]+sred[7];
  mu=s1*(1.f/128.f);
  inv=rsqrtf(s2*(1.f/128.f)-mu*mu+1e-5f);
  out[b*128+t]=(v-mu)*inv*ln4_g[t]+ln4_b[t];
}

extern "C" void kernel_launch(void* const* d_in, const int* in_sizes, int n_in,
                              void* d_out, int out_size)
{
  const float* node_obs=(const float*)d_in[0];
  const float* adj     =(const float*)d_in[1];
  const int*   agent_id=(const int*)  d_in[2];
  const float* emb     =(const float*)d_in[3];
  const float* lin1_w  =(const float*)d_in[4];
  const float* lin1_b  =(const float*)d_in[5];
  const float* ln1_g   =(const float*)d_in[6];
  const float* ln1_b   =(const float*)d_in[7];
  const float* linh_w  =(const float*)d_in[8];
  const float* linh_b  =(const float*)d_in[9];
  const float* lnh_g   =(const float*)d_in[10];
  const float* lnh_b   =(const float*)d_in[11];
  const float* fc2a_w  =(const float*)d_in[12];
  const float* fc2a_b  =(const float*)d_in[13];
  const float* fc2b_w  =(const float*)d_in[14];
  const float* fc2b_b  =(const float*)d_in[15];
  const float* fc3_w   =(const float*)d_in[16];
  const float* fc3_b   =(const float*)d_in[17];
  const float* ln3_g   =(const float*)d_in[18];
  const float* ln3_b   =(const float*)d_in[19];
  const float* fc4_w   =(const float*)d_in[20];
  const float* fc4_b   =(const float*)d_in[21];
  const float* ln4_g   =(const float*)d_in[22];
  const float* ln4_b   =(const float*)d_in[23];

  cudaFuncSetAttribute(gnn_k1, cudaFuncAttributeMaxDynamicSharedMemorySize, SMEM_BYTES);

  gnn_k1<<<512,512,SMEM_BYTES>>>(node_obs,adj,agent_id,emb,
                                 lin1_w,lin1_b,ln1_g,ln1_b,
                                 linh_w,linh_b,lnh_g,lnh_b,
                                 fc2a_w,fc2a_b,fc2b_w,fc2b_b);
  gnn_k2<<<1,256>>>();
  gnn_k3<<<512,128>>>(fc3_w,fc3_b,ln3_g,ln3_b,fc4_w,fc4_b,ln4_g,ln4_b,
                      agent_id,(float*)d_out);
}